// round 6
// baseline (speedup 1.0000x reference)
#include <cuda_runtime.h>
#include <cuda_bf16.h>
#include <cstdint>

#define B_    128
#define T_    25
#define L_    49
#define V_    10000
#define E_    512
#define H_    512
#define ENC_  512
#define BL_   (B_ * L_)      // 6272
#define BT_   (B_ * T_)      // 3200
#define KBIG_ 1536
#define VPAD_ 10112          // 158 * 64

typedef unsigned long long ull;

// ---------------- device scratch ----------------
__device__ float g_enc_proj[BL_ * H_];          // [6272][512]
__device__ float g_gates_pre[(size_t)BT_ * 4 * H_]; // [3200][2048] permuted cols
__device__ float g_W1T[H_ * 2560];              // k-major [512][2560]: [W_h | perm(W_hh)]
__device__ float g_W2T[H_ * 2048];              // k-major [512][2048]: perm(W_ih[:,512:])
__device__ float g_bsum[4 * H_];                // permuted
__device__ float g_big1[B_ * 2560];             // [128][hp(512) | gates_h(2048)]
__device__ float g_ctxT[ENC_ * B_];             // k-major [512][128]
__device__ float g_hT[(T_ + 1) * H_ * B_];      // 26 slots, k-major [512][128]
__device__ float g_c[2 * B_ * H_];
// bf16 split operands (A: hi|hi|lo, B: hi|lo|hi)
__device__ __align__(16) __nv_bfloat16 g_Wbig[(size_t)VPAD_ * KBIG_];
__device__ __align__(16) __nv_bfloat16 g_hbig[(size_t)T_ * B_ * KBIG_];
__device__ __align__(16) __nv_bfloat16 g_encA[(size_t)BL_ * KBIG_];
__device__ __align__(16) __nv_bfloat16 g_embX[(size_t)BT_ * KBIG_];
__device__ __align__(16) __nv_bfloat16 g_WeB[(size_t)H_ * KBIG_];
__device__ __align__(16) __nv_bfloat16 g_WihB[(size_t)(4 * H_) * KBIG_];

// ---------------- fast transcendentals ----------------
__device__ __forceinline__ float fex2(float x) {
    float y; asm("ex2.approx.ftz.f32 %0, %1;" : "=f"(y) : "f"(x)); return y;
}
__device__ __forceinline__ float frcp(float x) {
    float y; asm("rcp.approx.ftz.f32 %0, %1;" : "=f"(y) : "f"(x)); return y;
}
__device__ __forceinline__ float ftanh_hw(float x) {   // 1 MUFU, ~5e-4 abs
    float y; asm("tanh.approx.f32 %0, %1;" : "=f"(y) : "f"(x)); return y;
}
__device__ __forceinline__ float ftanh(float x) {      // precise (LSTM)
    float xc = fminf(fmaxf(x, -8.f), 8.f);
    float e = fex2(xc * 2.8853900817779268f);
    return (e - 1.f) * frcp(e + 1.f);
}
__device__ __forceinline__ float fsig(float x) {
    float xc = fminf(fmaxf(x, -30.f), 30.f);
    float e = fex2(-xc * 1.4426950408889634f);
    return frcp(1.f + e);
}

// ---------------- f32x2 helpers ----------------
__device__ __forceinline__ ull ld64s(const float* p) {
    return *reinterpret_cast<const ull*>(p);
}
__device__ __forceinline__ void fma2(ull& d, ull a, ull b) {
    asm("fma.rn.f32x2 %0, %1, %2, %0;" : "+l"(d) : "l"(a), "l"(b));
}
__device__ __forceinline__ ull pack2(float x) {
    ull r; asm("mov.b64 %0, {%1, %1};" : "=l"(r) : "f"(x)); return r;
}
__device__ __forceinline__ float lo2(ull v) { return __uint_as_float((unsigned)v); }
__device__ __forceinline__ float hi2(ull v) { return __uint_as_float((unsigned)(v >> 32)); }

// ---------------- mma.sync helpers ----------------
__device__ __forceinline__ uint32_t smem_u32(const void* p) {
    uint32_t a;
    asm("{ .reg .u64 t; cvta.to.shared.u64 t, %1; cvt.u32.u64 %0, t; }"
        : "=r"(a) : "l"(p));
    return a;
}
__device__ __forceinline__ void ldm_x4(uint32_t* r, uint32_t addr) {
    asm volatile("ldmatrix.sync.aligned.m8n8.x4.shared.b16 {%0,%1,%2,%3}, [%4];"
        : "=r"(r[0]), "=r"(r[1]), "=r"(r[2]), "=r"(r[3]) : "r"(addr));
}
__device__ __forceinline__ void mma_bf16(float* d, const uint32_t* a,
                                         uint32_t b0, uint32_t b1) {
    asm volatile("mma.sync.aligned.m16n8k16.row.col.f32.bf16.bf16.f32 "
        "{%0,%1,%2,%3}, {%4,%5,%6,%7}, {%8,%9}, {%0,%1,%2,%3};"
        : "+f"(d[0]), "+f"(d[1]), "+f"(d[2]), "+f"(d[3])
        : "r"(a[0]), "r"(a[1]), "r"(a[2]), "r"(a[3]), "r"(b0), "r"(b1));
}

// ---------------------------------------------------------------------------
// bf16-split HMMA GEMM: out[m,n] = sum_k A[m,k]*Bm[n,k] (+bias), K = 1536.
// CTA tile 128m x BN n (BN = 64 or 128), 8 warps (2m x 4n).
// ---------------------------------------------------------------------------
template<int BN>
__global__ void __launch_bounds__(256) mma_gemm(
    const __nv_bfloat16* __restrict__ A,
    const __nv_bfloat16* __restrict__ Bm,
    const float* __restrict__ bias,
    float* __restrict__ out, long ldout, int Nvalid)
{
    constexpr int FP = BN / 64;              // b-frag x4 loads per warp
    constexpr int ROWS = 128 + BN;
    __shared__ __align__(16) __nv_bfloat16 smt[2][ROWS][40];  // pitch 80B
    const int tid = threadIdx.x;
    const int l = tid & 31, wid = tid >> 5;
    const int wm = wid >> 2, wn = wid & 3;
    const int mbase = blockIdx.y * 128;
    const int nbase = blockIdx.x * BN;
    const __nv_bfloat16* Asrc = A + (size_t)mbase * KBIG_;
    const __nv_bfloat16* Bsrc = Bm + (size_t)nbase * KBIG_;

    float d[4][2 * FP][4];
#pragma unroll
    for (int i = 0; i < 4; i++)
#pragma unroll
        for (int j = 0; j < 2 * FP; j++)
#pragma unroll
            for (int q = 0; q < 4; q++) d[i][j][q] = 0.f;

    const uint32_t sb = smem_u32(smt);
    const int arow = wm * 64 + (l & 15);
    const int acol = (l >> 4) * 8;
    const int brow = wn * (BN / 4) + ((l >> 4) << 3) + (l & 7);
    const int bcol = ((l >> 3) & 1) * 8;

    auto ldglobal = [&](int c, int buf) {
#pragma unroll
        for (int q = 0; q < ROWS / 64; q++) {
            int idx = tid + q * 256;
            int r = idx >> 2;
            int cq = idx & 3;
            const __nv_bfloat16* s = (r < 128) ? (Asrc + (size_t)r * KBIG_)
                                               : (Bsrc + (size_t)(r - 128) * KBIG_);
            uint4 v = *(const uint4*)(s + c * 32 + cq * 8);
            *(uint4*)(&smt[buf][r][cq * 8]) = v;
        }
    };

    ldglobal(0, 0);
    __syncthreads();
#pragma unroll 1
    for (int c = 0; c < 48; c++) {
        const int buf = c & 1;
        if (c + 1 < 48) ldglobal(c + 1, buf ^ 1);
        const uint32_t base = sb + buf * (ROWS * 80);
#pragma unroll
        for (int s = 0; s < 2; s++) {
            uint32_t ar[4][4];
#pragma unroll
            for (int fm = 0; fm < 4; fm++)
                ldm_x4(ar[fm],
                       base + ((arow + fm * 16) * 40 + acol + s * 16) * 2);
#pragma unroll
            for (int fp = 0; fp < FP; fp++) {
                uint32_t br[4];
                ldm_x4(br, base + 128 * 80 +
                           ((brow + fp * 16) * 40 + bcol + s * 16) * 2);
#pragma unroll
                for (int fm = 0; fm < 4; fm++) {
                    mma_bf16(d[fm][fp * 2],     ar[fm], br[0], br[1]);
                    mma_bf16(d[fm][fp * 2 + 1], ar[fm], br[2], br[3]);
                }
            }
        }
        __syncthreads();
    }

#pragma unroll
    for (int fm = 0; fm < 4; fm++) {
        int m0 = mbase + wm * 64 + fm * 16 + (l >> 2);
#pragma unroll
        for (int fn = 0; fn < 2 * FP; fn++) {
            int n0 = nbase + wn * (BN / 4) + fn * 8 + (l & 3) * 2;
            if (n0 < Nvalid) {
                float b0 = bias ? bias[n0] : 0.f;
                float b1 = bias ? bias[n0 + 1] : 0.f;
                float2 v0 = make_float2(d[fm][fn][0] + b0, d[fm][fn][1] + b1);
                float2 v1 = make_float2(d[fm][fn][2] + b0, d[fm][fn][3] + b1);
                *(float2*)&out[(size_t)m0 * ldout + n0] = v0;
                *(float2*)&out[(size_t)(m0 + 8) * ldout + n0] = v1;
            }
        }
    }
}

// ---------------------------------------------------------------------------
// f32x2 GEMM core: 64m x 32n CTA tile, K=512, k-major operands (mstride=128).
// Thread: 4m (2 f32x2 pairs) x 2n.
// ---------------------------------------------------------------------------
__device__ __forceinline__ void gemm64_core(
    const float* __restrict__ XT, const float* __restrict__ WT, int nstride,
    float (*Xs)[64], float (*Ws)[32], int mbase, int nb, ull acc[2][2])
{
    const int tid = threadIdx.x;
    const int tx = tid & 15, ty = tid >> 4;
    acc[0][0] = acc[0][1] = acc[1][0] = acc[1][1] = 0ull;
    const int kx = tid >> 4, mw = (tid & 15) << 2;
    const int nw = (tid & 15) << 1;
#pragma unroll 1
    for (int k0 = 0; k0 < 512; k0 += 16) {
        *(float4*)&Xs[kx][mw] = *(const float4*)(XT + (k0 + kx) * 128 + mbase + mw);
        *(float2*)&Ws[kx][nw] = *(const float2*)(WT + (size_t)(k0 + kx) * nstride + nb + nw);
        __syncthreads();
#pragma unroll
        for (int kk = 0; kk < 16; kk++) {
            ull a0 = ld64s(&Xs[kk][ty * 4]);
            ull a1 = ld64s(&Xs[kk][ty * 4 + 2]);
            float2 bw = *(const float2*)&Ws[kk][tx * 2];
            ull b0 = pack2(bw.x), b1 = pack2(bw.y);
            fma2(acc[0][0], a0, b0);
            fma2(acc[0][1], a0, b1);
            fma2(acc[1][0], a1, b0);
            fma2(acc[1][1], a1, b1);
        }
        __syncthreads();
    }
}

// GEMM1: big1[b][0:2560] = h(t) @ [W_h | perm(W_hh)]^T.  grid(80, 2)
__global__ void __launch_bounds__(256) gemm1_k(const float* __restrict__ hTt) {
    __shared__ float Xs[16][64];
    __shared__ float Ws[16][32];
    const int nb = blockIdx.x * 32, mbase = blockIdx.y * 64;
    ull acc[2][2];
    gemm64_core(hTt, g_W1T, 2560, Xs, Ws, mbase, nb, acc);
    const int tx = threadIdx.x & 15, ty = threadIdx.x >> 4;
#pragma unroll
    for (int p = 0; p < 2; p++) {
        int m = mbase + ty * 4 + p * 2;
#pragma unroll
        for (int j = 0; j < 2; j++) {
            int n = nb + tx * 2 + j;
            g_big1[m * 2560 + n]       = lo2(acc[p][j]);
            g_big1[(m + 1) * 2560 + n] = hi2(acc[p][j]);
        }
    }
}

// GEMM2 + LSTM pointwise fused.  grid(64, 2)
__global__ void __launch_bounds__(256) gemm2_lstm(int t) {
    __shared__ float Xs[16][64];
    __shared__ float Ws[16][32];
    __shared__ float gs[64][33];
    const int nb = blockIdx.x * 32, mbase = blockIdx.y * 64;
    ull acc[2][2];
    gemm64_core(g_ctxT, g_W2T, 2048, Xs, Ws, mbase, nb, acc);

    const int tid = threadIdx.x;
    const int tx = tid & 15, ty = tid >> 4;
#pragma unroll
    for (int p = 0; p < 2; p++) {
        int bl = ty * 4 + p * 2;
        int b = mbase + bl;
#pragma unroll
        for (int j = 0; j < 2; j++) {
            int ln = tx * 2 + j;
            int n = nb + ln;
            gs[bl][ln] = lo2(acc[p][j]) + g_big1[b * 2560 + 512 + n]
                       + g_gates_pre[((size_t)(t * B_ + b)) * 2048 + n];
            gs[bl + 1][ln] = hi2(acc[p][j]) + g_big1[(b + 1) * 2560 + 512 + n]
                       + g_gates_pre[((size_t)(t * B_ + b + 1)) * 2048 + n];
        }
    }
    __syncthreads();

    // pointwise: 64 b x 8 units; cols are permuted (u*4 + gate)
#pragma unroll
    for (int q = 0; q < 2; q++) {
        int idx = tid + q * 256;
        int bl = idx >> 3, ul = idx & 7;
        int b = mbase + bl;
        int u = (nb >> 2) + ul;
        float gi = gs[bl][ul * 4 + 0];
        float gf = gs[bl][ul * 4 + 1];
        float gg = gs[bl][ul * 4 + 2];
        float go = gs[bl][ul * 4 + 3];
        float cn = fsig(gf) * g_c[(size_t)(t & 1) * (B_ * H_) + b * H_ + u]
                 + fsig(gi) * ftanh(gg);
        g_c[(size_t)((t + 1) & 1) * (B_ * H_) + b * H_ + u] = cn;
        float h = fsig(go) * ftanh(cn);
        g_hT[(size_t)(t + 1) * (H_ * B_) + (size_t)u * B_ + b] = h;
        __nv_bfloat16 h1 = __float2bfloat16(h);
        float h2 = h - __bfloat162float(h1);
        __nv_bfloat16* row = g_hbig + ((size_t)t * B_ + b) * KBIG_;
        row[u]        = h1;
        row[512 + u]  = h1;
        row[1024 + u] = __float2bfloat16(h2);
    }
}

// ---------------------------------------------------------------------------
// Attention: hp from big1[:, 0:512]; scores; softmax; ctx -> ctxT (k-major).
// ---------------------------------------------------------------------------
__global__ void __launch_bounds__(512) attn_kernel(
    const float* __restrict__ enc, const float* __restrict__ vattn) {
    const int b = blockIdx.x, tid = threadIdx.x;
    __shared__ float hp_s[H_];
    __shared__ float v_s[H_];
    __shared__ float sc[64];

    hp_s[tid] = g_big1[b * 2560 + tid];
    v_s[tid] = vattn[tid];
    __syncthreads();

    const int w = tid >> 5, lane = tid & 31;
    const float* ep = g_enc_proj + (size_t)b * L_ * H_;
    for (int l = w; l < L_; l += 16) {
        const float* row = ep + l * H_;
        float p = 0.f;
#pragma unroll
        for (int k = lane; k < H_; k += 32)
            p += ftanh_hw(hp_s[k] + row[k]) * v_s[k];
#pragma unroll
        for (int o = 16; o; o >>= 1) p += __shfl_xor_sync(0xffffffffu, p, o);
        if (lane == 0) sc[l] = p;
    }
    __syncthreads();

    if (tid < 32) {
        float v0 = sc[tid];
        float v1 = (tid < L_ - 32) ? sc[32 + tid] : -1e30f;
        float mx = fmaxf(v0, v1);
#pragma unroll
        for (int o = 16; o; o >>= 1) mx = fmaxf(mx, __shfl_xor_sync(0xffffffffu, mx, o));
        float e0 = fex2((v0 - mx) * 1.4426950408889634f);
        float e1 = (tid < L_ - 32) ? fex2((v1 - mx) * 1.4426950408889634f) : 0.f;
        float s = e0 + e1;
#pragma unroll
        for (int o = 16; o; o >>= 1) s += __shfl_xor_sync(0xffffffffu, s, o);
        float r = frcp(s);
        sc[tid] = e0 * r;
        if (tid < L_ - 32) sc[32 + tid] = e1 * r;
    }
    __syncthreads();

    const float* eb = enc + (size_t)b * L_ * ENC_;
    float a = 0.f;
#pragma unroll 7
    for (int l = 0; l < L_; l++) a += sc[l] * eb[l * ENC_ + tid];
    g_ctxT[(size_t)tid * B_ + b] = a;
}

// ---------------------------------------------------------------------------
// preamble kernels
// ---------------------------------------------------------------------------
__global__ void transp(const float* __restrict__ in, float* __restrict__ out,
                       int R, int C, int istride, int ostride) {
    __shared__ float t[32][33];
    int c0 = blockIdx.x * 32, r0 = blockIdx.y * 32;
#pragma unroll
    for (int i = threadIdx.y; i < 32; i += 8) {
        int r = r0 + i, c = c0 + threadIdx.x;
        t[i][threadIdx.x] = (r < R && c < C) ? in[(size_t)r * istride + c] : 0.f;
    }
    __syncthreads();
#pragma unroll
    for (int i = threadIdx.y; i < 32; i += 8) {
        int c = c0 + i, r = r0 + threadIdx.x;
        if (c < C && r < R) out[(size_t)c * ostride + r] = t[threadIdx.x][i];
    }
}

// permuted-gate transpose: out[k*out_ld + perm(r)] = in[r*in_ld + col_off + k]
// perm(r): r = g*512 + u  ->  n = u*4 + g
__global__ void transp_pg(const float* __restrict__ in, float* __restrict__ out,
                          int in_ld, int col_off, int out_ld) {
    __shared__ float t[32][33];
    int c0 = blockIdx.x * 32, r0 = blockIdx.y * 32;   // c = k, r = gate row
#pragma unroll
    for (int i = threadIdx.y; i < 32; i += 8)
        t[i][threadIdx.x] = in[(size_t)(r0 + i) * in_ld + col_off + c0 + threadIdx.x];
    __syncthreads();
#pragma unroll
    for (int i = threadIdx.y; i < 32; i += 8) {
        int k = c0 + i;
        int r = r0 + threadIdx.x;
        int n = ((r & 511) << 2) | (r >> 9);
        out[(size_t)k * out_ld + n] = t[threadIdx.x][i];
    }
}

__global__ void bias_sum_perm(const float* __restrict__ bi,
                              const float* __restrict__ bh) {
    int n = blockIdx.x * 256 + threadIdx.x;
    int o = ((n & 3) << 9) | (n >> 2);
    g_bsum[n] = bi[o] + bh[o];
}

// B-split: row n -> (hi | lo | hi)
__global__ void bsplit(const float* __restrict__ src, int ldsrc,
                       __nv_bfloat16* __restrict__ dst, int Nsrc) {
    int n = blockIdx.x, j = threadIdx.x;
    float w = (n < Nsrc) ? src[(size_t)n * ldsrc + j] : 0.f;
    __nv_bfloat16 hi = __float2bfloat16(w);
    float lo = w - __bfloat162float(hi);
    __nv_bfloat16* row = dst + (size_t)n * KBIG_;
    row[j] = hi;
    row[512 + j] = __float2bfloat16(lo);
    row[1024 + j] = hi;
}

// permuted B-split for W_ih emb-part: dst row n = split(W_ih[perm_orig(n)][0:512])
__global__ void bsplit_perm(const float* __restrict__ W_ih) {
    int n = blockIdx.x, j = threadIdx.x;
    int o = ((n & 3) << 9) | (n >> 2);
    float w = W_ih[(size_t)o * 1024 + j];
    __nv_bfloat16 hi = __float2bfloat16(w);
    float lo = w - __bfloat162float(hi);
    __nv_bfloat16* row = g_WihB + (size_t)n * KBIG_;
    row[j] = hi;
    row[512 + j] = __float2bfloat16(lo);
    row[1024 + j] = hi;
}

// A-split: row m -> (hi | hi | lo)
__global__ void asplit(const float* __restrict__ src, __nv_bfloat16* __restrict__ dst) {
    int m = blockIdx.x, j = threadIdx.x;
    float v = src[(size_t)m * 512 + j];
    __nv_bfloat16 hi = __float2bfloat16(v);
    float lo = v - __bfloat162float(hi);
    __nv_bfloat16* row = dst + (size_t)m * KBIG_;
    row[j] = hi;
    row[512 + j] = hi;
    row[1024 + j] = __float2bfloat16(lo);
}

__global__ void emb_gather(const int* __restrict__ cap, const float* __restrict__ emb) {
    int m = blockIdx.x;
    int b = m & 127, t = m >> 7;
    int w = cap[b * T_ + t];
    int j = threadIdx.x;
    float v = emb[(size_t)w * E_ + j];
    __nv_bfloat16 hi = __float2bfloat16(v);
    float lo = v - __bfloat162float(hi);
    __nv_bfloat16* row = g_embX + (size_t)m * KBIG_;
    row[j] = hi;
    row[512 + j] = hi;
    row[1024 + j] = __float2bfloat16(lo);
}

__global__ void zero_state() {
    int i = blockIdx.x * 256 + threadIdx.x;
    g_hT[i] = 0.f;
    g_c[i] = 0.f;
}

// ---------------------------------------------------------------------------
extern "C" void kernel_launch(void* const* d_in, const int* in_sizes, int n_in,
                              void* d_out, int out_size) {
    const int*   captions = (const int*)d_in[0];
    const float* enc      = (const float*)d_in[1];
    const float* emb      = (const float*)d_in[2];
    const float* W_h      = (const float*)d_in[3];
    const float* W_e      = (const float*)d_in[4];
    const float* v_attn   = (const float*)d_in[5];
    const float* W_ih     = (const float*)d_in[6];
    const float* W_hh     = (const float*)d_in[7];
    const float* b_ih     = (const float*)d_in[8];
    const float* b_hh     = (const float*)d_in[9];
    const float* W_fc     = (const float*)d_in[10];
    const float* b_fc     = (const float*)d_in[11];
    float* out = (float*)d_out;

    static cudaStream_t s2 = nullptr, s3 = nullptr;
    static cudaEvent_t evStart = nullptr, evG = nullptr, evH = nullptr,
                       evJ2 = nullptr;
    if (!s2) {
        cudaStreamCreateWithFlags(&s2, cudaStreamNonBlocking);
        cudaStreamCreateWithFlags(&s3, cudaStreamNonBlocking);
        cudaEventCreateWithFlags(&evStart, cudaEventDisableTiming);
        cudaEventCreateWithFlags(&evG,  cudaEventDisableTiming);
        cudaEventCreateWithFlags(&evH,  cudaEventDisableTiming);
        cudaEventCreateWithFlags(&evJ2, cudaEventDisableTiming);
    }

    float *enc_proj, *gates_pre, *W1T, *W2T, *bsum, *hT;
    __nv_bfloat16 *Wbig, *hbig, *encA, *embX, *WeB, *WihB;
    cudaGetSymbolAddress((void**)&enc_proj,  g_enc_proj);
    cudaGetSymbolAddress((void**)&gates_pre, g_gates_pre);
    cudaGetSymbolAddress((void**)&W1T,       g_W1T);
    cudaGetSymbolAddress((void**)&W2T,       g_W2T);
    cudaGetSymbolAddress((void**)&bsum,      g_bsum);
    cudaGetSymbolAddress((void**)&hT,        g_hT);
    cudaGetSymbolAddress((void**)&Wbig,      g_Wbig);
    cudaGetSymbolAddress((void**)&hbig,      g_hbig);
    cudaGetSymbolAddress((void**)&encA,      g_encA);
    cudaGetSymbolAddress((void**)&embX,      g_embX);
    cudaGetSymbolAddress((void**)&WeB,       g_WeB);
    cudaGetSymbolAddress((void**)&WihB,      g_WihB);

    const dim3 tb(32, 8);

    // fork: s2 and s3 join the capture BEFORE any of their work
    zero_state<<<256, 256>>>();
    cudaEventRecord(evStart, 0);
    cudaStreamWaitEvent(s2, evStart, 0);
    cudaStreamWaitEvent(s3, evStart, 0);

    // s2: W_fc split (feeds logits)
    bsplit<<<VPAD_, 512, 0, s2>>>(W_fc, H_, Wbig, V_);

    // s3: gates_pre pipeline (permuted columns)
    bias_sum_perm<<<8, 256, 0, s3>>>(b_ih, b_hh);
    emb_gather<<<BT_, 512, 0, s3>>>(captions, emb);
    bsplit_perm<<<4 * H_, 512, 0, s3>>>(W_ih);
    mma_gemm<128><<<dim3(16, T_), 256, 0, s3>>>(embX, WihB, bsum, gates_pre,
                                                4L * H_, 4 * H_);
    cudaEventRecord(evG, s3);

    // s1: chain weights + enc_proj
    transp<<<dim3(16, 16), tb>>>(W_h, W1T, H_, H_, H_, 2560);       // cols 0-511
    transp_pg<<<dim3(16, 64), tb>>>(W_hh, W1T + 512, 512, 0, 2560); // cols 512+
    transp_pg<<<dim3(16, 64), tb>>>(W_ih, W2T, 1024, 512, 2048);
    bsplit<<<H_, 512>>>(W_e, ENC_, WeB, H_);
    asplit<<<BL_, 512>>>(enc, encA);
    mma_gemm<128><<<dim3(4, BL_ / 128), 256>>>(encA, WeB, nullptr, enc_proj,
                                               (long)H_, H_);

    for (int t = 0; t < T_; t++) {
        gemm1_k<<<dim3(80, 2), 256>>>(hT + (size_t)t * H_ * B_);
        attn_kernel<<<B_, 512>>>(enc, v_attn);
        if (t == 0) cudaStreamWaitEvent(0, evG, 0);   // join s3 (gates_pre)
        gemm2_lstm<<<dim3(64, 2), 256>>>(t);
        cudaEventRecord(evH, 0);
        cudaStreamWaitEvent(s2, evH, 0);
        // logits on s2 (HMMA, 158 CTAs), overlapped with next step's chain
        mma_gemm<64><<<dim3(VPAD_ / 64, 1), 256, 0, s2>>>(
            hbig + (size_t)t * B_ * KBIG_, Wbig, b_fc,
            out + (size_t)t * V_, (long)(T_ * V_), V_);
    }
    cudaEventRecord(evJ2, s2);                        // join s2
    cudaStreamWaitEvent(0, evJ2, 0);
}

// round 7
// speedup vs baseline: 1.1566x; 1.1566x over previous
#include <cuda_runtime.h>
#include <cuda_fp16.h>
#include <cstdint>

#define B_    128
#define T_    25
#define L_    49
#define V_    10000
#define E_    512
#define H_    512
#define ENC_  512
#define BL_   (B_ * L_)      // 6272
#define BT_   (B_ * T_)      // 3200
#define VPAD_ 10112          // 158 * 64

typedef unsigned long long ull;

// ---------------- device scratch ----------------
__device__ float g_enc_proj[BL_ * H_];          // [6272][512]
__device__ float g_gates_pre[(size_t)BT_ * 4 * H_]; // [3200][2048] permuted cols
__device__ float g_W1T[H_ * 2560];              // k-major [512][2560]: [W_h | perm(W_hh)]
__device__ float g_W2T[H_ * 2048];              // k-major [512][2048]: perm(W_ih[:,512:])
__device__ float g_bsum[4 * H_];                // permuted
__device__ float g_big1[B_ * 2560];             // [128][hp(512) | gates_h(2048)]
__device__ float g_ctxT[ENC_ * B_];             // k-major [512][128]
__device__ float g_hT[(T_ + 1) * H_ * B_];      // 26 slots, k-major [512][128]
__device__ float g_c[2 * B_ * H_];
// fp16 tensor-GEMM operands
__device__ __align__(16) __half g_Wbig[(size_t)VPAD_ * 1024];   // [w1 | w2]
__device__ __align__(16) __half g_hbig[(size_t)T_ * B_ * 1024]; // [h1 | h1]
__device__ __align__(16) __half g_encA[(size_t)BL_ * 512];
__device__ __align__(16) __half g_embX[(size_t)BT_ * 512];
__device__ __align__(16) __half g_WeB[(size_t)H_ * 512];
__device__ __align__(16) __half g_WihB[(size_t)(4 * H_) * 512];

// ---------------- fast transcendentals ----------------
__device__ __forceinline__ float fex2(float x) {
    float y; asm("ex2.approx.ftz.f32 %0, %1;" : "=f"(y) : "f"(x)); return y;
}
__device__ __forceinline__ float frcp(float x) {
    float y; asm("rcp.approx.ftz.f32 %0, %1;" : "=f"(y) : "f"(x)); return y;
}
__device__ __forceinline__ float ftanh_hw(float x) {   // 1 MUFU, ~5e-4 abs
    float y; asm("tanh.approx.f32 %0, %1;" : "=f"(y) : "f"(x)); return y;
}
__device__ __forceinline__ float ftanh(float x) {      // precise (LSTM)
    float xc = fminf(fmaxf(x, -8.f), 8.f);
    float e = fex2(xc * 2.8853900817779268f);
    return (e - 1.f) * frcp(e + 1.f);
}
__device__ __forceinline__ float fsig(float x) {
    float xc = fminf(fmaxf(x, -30.f), 30.f);
    float e = fex2(-xc * 1.4426950408889634f);
    return frcp(1.f + e);
}

// ---------------- f32x2 helpers ----------------
__device__ __forceinline__ ull ld64s(const float* p) {
    return *reinterpret_cast<const ull*>(p);
}
__device__ __forceinline__ void fma2(ull& d, ull a, ull b) {
    asm("fma.rn.f32x2 %0, %1, %2, %0;" : "+l"(d) : "l"(a), "l"(b));
}
__device__ __forceinline__ ull pack2(float x) {
    ull r; asm("mov.b64 %0, {%1, %1};" : "=l"(r) : "f"(x)); return r;
}
__device__ __forceinline__ float lo2(ull v) { return __uint_as_float((unsigned)v); }
__device__ __forceinline__ float hi2(ull v) { return __uint_as_float((unsigned)(v >> 32)); }

// ---------------- mma.sync helpers ----------------
__device__ __forceinline__ uint32_t smem_u32(const void* p) {
    uint32_t a;
    asm("{ .reg .u64 t; cvta.to.shared.u64 t, %1; cvt.u32.u64 %0, t; }"
        : "=r"(a) : "l"(p));
    return a;
}
__device__ __forceinline__ void ldm_x4(uint32_t* r, uint32_t addr) {
    asm volatile("ldmatrix.sync.aligned.m8n8.x4.shared.b16 {%0,%1,%2,%3}, [%4];"
        : "=r"(r[0]), "=r"(r[1]), "=r"(r[2]), "=r"(r[3]) : "r"(addr));
}
__device__ __forceinline__ void mma_f16(float* d, const uint32_t* a,
                                        uint32_t b0, uint32_t b1) {
    asm volatile("mma.sync.aligned.m16n8k16.row.col.f32.f16.f16.f32 "
        "{%0,%1,%2,%3}, {%4,%5,%6,%7}, {%8,%9}, {%0,%1,%2,%3};"
        : "+f"(d[0]), "+f"(d[1]), "+f"(d[2]), "+f"(d[3])
        : "r"(a[0]), "r"(a[1]), "r"(a[2]), "r"(a[3]), "r"(b0), "r"(b1));
}

// ---------------------------------------------------------------------------
// fp16 HMMA GEMM: out[m,n] = sum_k A[m,k]*Bm[n,k] (+bias), K = KLEN.
// A,B: row-major [.][KLEN] fp16. CTA tile 128m x BN, 8 warps (2m x 4n).
// ---------------------------------------------------------------------------
template<int BN, int KLEN>
__global__ void __launch_bounds__(256) mma_gemm(
    const __half* __restrict__ A,
    const __half* __restrict__ Bm,
    const float* __restrict__ bias,
    float* __restrict__ out, long ldout, int Nvalid)
{
    constexpr int FP = BN / 64;
    constexpr int ROWS = 128 + BN;
    constexpr int NCH = KLEN / 32;
    __shared__ __align__(16) __half smt[2][ROWS][40];  // pitch 80B
    const int tid = threadIdx.x;
    const int l = tid & 31, wid = tid >> 5;
    const int wm = wid >> 2, wn = wid & 3;
    const int mbase = blockIdx.y * 128;
    const int nbase = blockIdx.x * BN;
    const __half* Asrc = A + (size_t)mbase * KLEN;
    const __half* Bsrc = Bm + (size_t)nbase * KLEN;

    float d[4][2 * FP][4];
#pragma unroll
    for (int i = 0; i < 4; i++)
#pragma unroll
        for (int j = 0; j < 2 * FP; j++)
#pragma unroll
            for (int q = 0; q < 4; q++) d[i][j][q] = 0.f;

    const uint32_t sb = smem_u32(smt);
    const int arow = wm * 64 + (l & 15);
    const int acol = (l >> 4) * 8;
    const int brow = wn * (BN / 4) + ((l >> 4) << 3) + (l & 7);
    const int bcol = ((l >> 3) & 1) * 8;

    auto ldglobal = [&](int c, int buf) {
#pragma unroll
        for (int q = 0; q < ROWS / 64; q++) {
            int idx = tid + q * 256;
            int r = idx >> 2;
            int cq = idx & 3;
            const __half* s = (r < 128) ? (Asrc + (size_t)r * KLEN)
                                        : (Bsrc + (size_t)(r - 128) * KLEN);
            uint4 v = *(const uint4*)(s + c * 32 + cq * 8);
            *(uint4*)(&smt[buf][r][cq * 8]) = v;
        }
    };

    ldglobal(0, 0);
    __syncthreads();
#pragma unroll 1
    for (int c = 0; c < NCH; c++) {
        const int buf = c & 1;
        if (c + 1 < NCH) ldglobal(c + 1, buf ^ 1);
        const uint32_t base = sb + buf * (ROWS * 80);
#pragma unroll
        for (int s = 0; s < 2; s++) {
            uint32_t ar[4][4];
#pragma unroll
            for (int fm = 0; fm < 4; fm++)
                ldm_x4(ar[fm],
                       base + ((arow + fm * 16) * 40 + acol + s * 16) * 2);
#pragma unroll
            for (int fp = 0; fp < FP; fp++) {
                uint32_t br[4];
                ldm_x4(br, base + 128 * 80 +
                           ((brow + fp * 16) * 40 + bcol + s * 16) * 2);
#pragma unroll
                for (int fm = 0; fm < 4; fm++) {
                    mma_f16(d[fm][fp * 2],     ar[fm], br[0], br[1]);
                    mma_f16(d[fm][fp * 2 + 1], ar[fm], br[2], br[3]);
                }
            }
        }
        __syncthreads();
    }

#pragma unroll
    for (int fm = 0; fm < 4; fm++) {
        int m0 = mbase + wm * 64 + fm * 16 + (l >> 2);
#pragma unroll
        for (int fn = 0; fn < 2 * FP; fn++) {
            int n0 = nbase + wn * (BN / 4) + fn * 8 + (l & 3) * 2;
            if (n0 < Nvalid) {
                float b0 = bias ? bias[n0] : 0.f;
                float b1 = bias ? bias[n0 + 1] : 0.f;
                float2 v0 = make_float2(d[fm][fn][0] + b0, d[fm][fn][1] + b1);
                float2 v1 = make_float2(d[fm][fn][2] + b0, d[fm][fn][3] + b1);
                *(float2*)&out[(size_t)m0 * ldout + n0] = v0;
                *(float2*)&out[(size_t)(m0 + 8) * ldout + n0] = v1;
            }
        }
    }
}

// ---------------------------------------------------------------------------
// f32x2 GEMM core: 64m x 32n CTA tile, K=512, k-major operands (mstride=128).
// ---------------------------------------------------------------------------
__device__ __forceinline__ void gemm64_core(
    const float* __restrict__ XT, const float* __restrict__ WT, int nstride,
    float (*Xs)[64], float (*Ws)[32], int mbase, int nb, ull acc[2][2])
{
    const int tid = threadIdx.x;
    const int tx = tid & 15, ty = tid >> 4;
    acc[0][0] = acc[0][1] = acc[1][0] = acc[1][1] = 0ull;
    const int kx = tid >> 4, mw = (tid & 15) << 2;
    const int nw = (tid & 15) << 1;
#pragma unroll 1
    for (int k0 = 0; k0 < 512; k0 += 16) {
        *(float4*)&Xs[kx][mw] = *(const float4*)(XT + (k0 + kx) * 128 + mbase + mw);
        *(float2*)&Ws[kx][nw] = *(const float2*)(WT + (size_t)(k0 + kx) * nstride + nb + nw);
        __syncthreads();
#pragma unroll
        for (int kk = 0; kk < 16; kk++) {
            ull a0 = ld64s(&Xs[kk][ty * 4]);
            ull a1 = ld64s(&Xs[kk][ty * 4 + 2]);
            float2 bw = *(const float2*)&Ws[kk][tx * 2];
            ull b0 = pack2(bw.x), b1 = pack2(bw.y);
            fma2(acc[0][0], a0, b0);
            fma2(acc[0][1], a0, b1);
            fma2(acc[1][0], a1, b0);
            fma2(acc[1][1], a1, b1);
        }
        __syncthreads();
    }
}

// GEMM1: big1[b][0:2560] = h(t) @ [W_h | perm(W_hh)]^T.  grid(80, 2)
__global__ void __launch_bounds__(256) gemm1_k(const float* __restrict__ hTt) {
    __shared__ float Xs[16][64];
    __shared__ float Ws[16][32];
    const int nb = blockIdx.x * 32, mbase = blockIdx.y * 64;
    ull acc[2][2];
    gemm64_core(hTt, g_W1T, 2560, Xs, Ws, mbase, nb, acc);
    const int tx = threadIdx.x & 15, ty = threadIdx.x >> 4;
#pragma unroll
    for (int p = 0; p < 2; p++) {
        int m = mbase + ty * 4 + p * 2;
#pragma unroll
        for (int j = 0; j < 2; j++) {
            int n = nb + tx * 2 + j;
            g_big1[m * 2560 + n]       = lo2(acc[p][j]);
            g_big1[(m + 1) * 2560 + n] = hi2(acc[p][j]);
        }
    }
}

// GEMM2 + LSTM pointwise fused.  grid(64, 2)
__global__ void __launch_bounds__(256) gemm2_lstm(int t) {
    __shared__ float Xs[16][64];
    __shared__ float Ws[16][32];
    __shared__ float gs[64][33];
    const int nb = blockIdx.x * 32, mbase = blockIdx.y * 64;
    ull acc[2][2];
    gemm64_core(g_ctxT, g_W2T, 2048, Xs, Ws, mbase, nb, acc);

    const int tid = threadIdx.x;
    const int tx = tid & 15, ty = tid >> 4;
#pragma unroll
    for (int p = 0; p < 2; p++) {
        int bl = ty * 4 + p * 2;
        int b = mbase + bl;
#pragma unroll
        for (int j = 0; j < 2; j++) {
            int ln = tx * 2 + j;
            int n = nb + ln;
            gs[bl][ln] = lo2(acc[p][j]) + g_big1[b * 2560 + 512 + n]
                       + g_gates_pre[((size_t)(t * B_ + b)) * 2048 + n];
            gs[bl + 1][ln] = hi2(acc[p][j]) + g_big1[(b + 1) * 2560 + 512 + n]
                       + g_gates_pre[((size_t)(t * B_ + b + 1)) * 2048 + n];
        }
    }
    __syncthreads();

    // pointwise: 64 b x 8 units; cols are permuted (u*4 + gate)
#pragma unroll
    for (int q = 0; q < 2; q++) {
        int idx = tid + q * 256;
        int bl = idx >> 3, ul = idx & 7;
        int b = mbase + bl;
        int u = (nb >> 2) + ul;
        float gi = gs[bl][ul * 4 + 0];
        float gf = gs[bl][ul * 4 + 1];
        float gg = gs[bl][ul * 4 + 2];
        float go = gs[bl][ul * 4 + 3];
        float cn = fsig(gf) * g_c[(size_t)(t & 1) * (B_ * H_) + b * H_ + u]
                 + fsig(gi) * ftanh(gg);
        g_c[(size_t)((t + 1) & 1) * (B_ * H_) + b * H_ + u] = cn;
        float h = fsig(go) * ftanh(cn);
        g_hT[(size_t)(t + 1) * (H_ * B_) + (size_t)u * B_ + b] = h;
        __half h1 = __float2half_rn(h);
        __half* row = g_hbig + ((size_t)t * B_ + b) * 1024;
        row[u]       = h1;
        row[512 + u] = h1;
    }
}

// ---------------------------------------------------------------------------
// Attention: hp from big1[:, 0:512]; scores; softmax; ctx -> ctxT (k-major).
// ---------------------------------------------------------------------------
__global__ void __launch_bounds__(512) attn_kernel(
    const float* __restrict__ enc, const float* __restrict__ vattn) {
    const int b = blockIdx.x, tid = threadIdx.x;
    __shared__ float hp_s[H_];
    __shared__ float v_s[H_];
    __shared__ float sc[64];

    hp_s[tid] = g_big1[b * 2560 + tid];
    v_s[tid] = vattn[tid];
    __syncthreads();

    const int w = tid >> 5, lane = tid & 31;
    const float* ep = g_enc_proj + (size_t)b * L_ * H_;
    for (int l = w; l < L_; l += 16) {
        const float* row = ep + l * H_;
        float p = 0.f;
#pragma unroll
        for (int k = lane; k < H_; k += 32)
            p += ftanh_hw(hp_s[k] + row[k]) * v_s[k];
#pragma unroll
        for (int o = 16; o; o >>= 1) p += __shfl_xor_sync(0xffffffffu, p, o);
        if (lane == 0) sc[l] = p;
    }
    __syncthreads();

    if (tid < 32) {
        float v0 = sc[tid];
        float v1 = (tid < L_ - 32) ? sc[32 + tid] : -1e30f;
        float mx = fmaxf(v0, v1);
#pragma unroll
        for (int o = 16; o; o >>= 1) mx = fmaxf(mx, __shfl_xor_sync(0xffffffffu, mx, o));
        float e0 = fex2((v0 - mx) * 1.4426950408889634f);
        float e1 = (tid < L_ - 32) ? fex2((v1 - mx) * 1.4426950408889634f) : 0.f;
        float s = e0 + e1;
#pragma unroll
        for (int o = 16; o; o >>= 1) s += __shfl_xor_sync(0xffffffffu, s, o);
        float r = frcp(s);
        sc[tid] = e0 * r;
        if (tid < L_ - 32) sc[32 + tid] = e1 * r;
    }
    __syncthreads();

    const float* eb = enc + (size_t)b * L_ * ENC_;
    float a = 0.f;
#pragma unroll 7
    for (int l = 0; l < L_; l++) a += sc[l] * eb[l * ENC_ + tid];
    g_ctxT[(size_t)tid * B_ + b] = a;
}

// ---------------------------------------------------------------------------
// preamble kernels
// ---------------------------------------------------------------------------
__global__ void transp(const float* __restrict__ in, float* __restrict__ out,
                       int R, int C, int istride, int ostride) {
    __shared__ float t[32][33];
    int c0 = blockIdx.x * 32, r0 = blockIdx.y * 32;
#pragma unroll
    for (int i = threadIdx.y; i < 32; i += 8) {
        int r = r0 + i, c = c0 + threadIdx.x;
        t[i][threadIdx.x] = (r < R && c < C) ? in[(size_t)r * istride + c] : 0.f;
    }
    __syncthreads();
#pragma unroll
    for (int i = threadIdx.y; i < 32; i += 8) {
        int c = c0 + i, r = r0 + threadIdx.x;
        if (c < C && r < R) out[(size_t)c * ostride + r] = t[threadIdx.x][i];
    }
}

// permuted-gate transpose: out[k*out_ld + perm(r)] = in[r*in_ld + col_off + k]
__global__ void transp_pg(const float* __restrict__ in, float* __restrict__ out,
                          int in_ld, int col_off, int out_ld) {
    __shared__ float t[32][33];
    int c0 = blockIdx.x * 32, r0 = blockIdx.y * 32;
#pragma unroll
    for (int i = threadIdx.y; i < 32; i += 8)
        t[i][threadIdx.x] = in[(size_t)(r0 + i) * in_ld + col_off + c0 + threadIdx.x];
    __syncthreads();
#pragma unroll
    for (int i = threadIdx.y; i < 32; i += 8) {
        int k = c0 + i;
        int r = r0 + threadIdx.x;
        int n = ((r & 511) << 2) | (r >> 9);
        out[(size_t)k * out_ld + n] = t[threadIdx.x][i];
    }
}

__global__ void bias_sum_perm(const float* __restrict__ bi,
                              const float* __restrict__ bh) {
    int n = blockIdx.x * 256 + threadIdx.x;
    int o = ((n & 3) << 9) | (n >> 2);
    g_bsum[n] = bi[o] + bh[o];
}

// W_fc 2-term fp16 split: row n -> [w1 | w2]
__global__ void wfc_split(const float* __restrict__ W_fc) {
    int n = blockIdx.x, j = threadIdx.x;
    float w = (n < V_) ? W_fc[(size_t)n * H_ + j] : 0.f;
    __half w1 = __float2half_rn(w);
    float lo = w - __half2float(w1);
    __half* row = g_Wbig + (size_t)n * 1024;
    row[j] = w1;
    row[512 + j] = __float2half_rn(lo);
}

// single-term fp16 conversion, row-major [R][512]
__global__ void h16_conv(const float* __restrict__ src, __half* __restrict__ dst) {
    int m = blockIdx.x, j = threadIdx.x;
    dst[(size_t)m * 512 + j] = __float2half_rn(src[(size_t)m * 512 + j]);
}

// permuted single-term fp16 for W_ih emb-part rows
__global__ void wih_emb_conv(const float* __restrict__ W_ih) {
    int n = blockIdx.x, j = threadIdx.x;
    int o = ((n & 3) << 9) | (n >> 2);
    g_WihB[(size_t)n * 512 + j] = __float2half_rn(W_ih[(size_t)o * 1024 + j]);
}

// embedding gather -> fp16
__global__ void emb_gather(const int* __restrict__ cap, const float* __restrict__ emb) {
    int m = blockIdx.x;
    int b = m & 127, t = m >> 7;
    int w = cap[b * T_ + t];
    int j = threadIdx.x;
    g_embX[(size_t)m * 512 + j] = __float2half_rn(emb[(size_t)w * E_ + j]);
}

__global__ void zero_state() {
    int i = blockIdx.x * 256 + threadIdx.x;
    g_hT[i] = 0.f;
    g_c[i] = 0.f;
}

// ---------------------------------------------------------------------------
extern "C" void kernel_launch(void* const* d_in, const int* in_sizes, int n_in,
                              void* d_out, int out_size) {
    const int*   captions = (const int*)d_in[0];
    const float* enc      = (const float*)d_in[1];
    const float* emb      = (const float*)d_in[2];
    const float* W_h      = (const float*)d_in[3];
    const float* W_e      = (const float*)d_in[4];
    const float* v_attn   = (const float*)d_in[5];
    const float* W_ih     = (const float*)d_in[6];
    const float* W_hh     = (const float*)d_in[7];
    const float* b_ih     = (const float*)d_in[8];
    const float* b_hh     = (const float*)d_in[9];
    const float* W_fc     = (const float*)d_in[10];
    const float* b_fc     = (const float*)d_in[11];
    float* out = (float*)d_out;

    static cudaStream_t s2 = nullptr, s3 = nullptr;
    static cudaEvent_t evStart = nullptr, evG = nullptr, evH = nullptr,
                       evJ2 = nullptr;
    if (!s2) {
        cudaStreamCreateWithFlags(&s2, cudaStreamNonBlocking);
        cudaStreamCreateWithFlags(&s3, cudaStreamNonBlocking);
        cudaEventCreateWithFlags(&evStart, cudaEventDisableTiming);
        cudaEventCreateWithFlags(&evG,  cudaEventDisableTiming);
        cudaEventCreateWithFlags(&evH,  cudaEventDisableTiming);
        cudaEventCreateWithFlags(&evJ2, cudaEventDisableTiming);
    }

    float *enc_proj, *gates_pre, *W1T, *W2T, *bsum, *hT;
    __half *Wbig, *hbig, *encA, *embX, *WeB, *WihB;
    cudaGetSymbolAddress((void**)&enc_proj,  g_enc_proj);
    cudaGetSymbolAddress((void**)&gates_pre, g_gates_pre);
    cudaGetSymbolAddress((void**)&W1T,       g_W1T);
    cudaGetSymbolAddress((void**)&W2T,       g_W2T);
    cudaGetSymbolAddress((void**)&bsum,      g_bsum);
    cudaGetSymbolAddress((void**)&hT,        g_hT);
    cudaGetSymbolAddress((void**)&Wbig,      g_Wbig);
    cudaGetSymbolAddress((void**)&hbig,      g_hbig);
    cudaGetSymbolAddress((void**)&encA,      g_encA);
    cudaGetSymbolAddress((void**)&embX,      g_embX);
    cudaGetSymbolAddress((void**)&WeB,       g_WeB);
    cudaGetSymbolAddress((void**)&WihB,      g_WihB);

    const dim3 tb(32, 8);

    // fork: s2 and s3 join the capture BEFORE any of their work
    zero_state<<<256, 256>>>();
    cudaEventRecord(evStart, 0);
    cudaStreamWaitEvent(s2, evStart, 0);
    cudaStreamWaitEvent(s3, evStart, 0);

    // s2: W_fc 2-term split (feeds logits)
    wfc_split<<<VPAD_, 512, 0, s2>>>(W_fc);

    // s3: gates_pre pipeline (fp16 single-term, permuted columns)
    bias_sum_perm<<<8, 256, 0, s3>>>(b_ih, b_hh);
    emb_gather<<<BT_, 512, 0, s3>>>(captions, emb);
    wih_emb_conv<<<4 * H_, 512, 0, s3>>>(W_ih);
    mma_gemm<128, 512><<<dim3(16, T_), 256, 0, s3>>>(embX, WihB, bsum,
                                                     gates_pre, 4L * H_, 4 * H_);
    cudaEventRecord(evG, s3);

    // s1: chain weights + enc_proj (fp16 single-term)
    transp<<<dim3(16, 16), tb>>>(W_h, W1T, H_, H_, H_, 2560);       // cols 0-511
    transp_pg<<<dim3(16, 64), tb>>>(W_hh, W1T + 512, 512, 0, 2560); // cols 512+
    transp_pg<<<dim3(16, 64), tb>>>(W_ih, W2T, 1024, 512, 2048);
    h16_conv<<<H_, 512>>>(W_e, WeB);
    h16_conv<<<BL_, 512>>>(enc, encA);
    mma_gemm<128, 512><<<dim3(4, BL_ / 128), 256>>>(encA, WeB, nullptr,
                                                    enc_proj, (long)H_, H_);

    for (int t = 0; t < T_; t++) {
        gemm1_k<<<dim3(80, 2), 256>>>(hT + (size_t)t * H_ * B_);
        attn_kernel<<<B_, 512>>>(enc, v_attn);
        if (t == 0) cudaStreamWaitEvent(0, evG, 0);   // join s3 (gates_pre)
        gemm2_lstm<<<dim3(64, 2), 256>>>(t);
        cudaEventRecord(evH, 0);
        cudaStreamWaitEvent(s2, evH, 0);
        // logits on s2 (fp16 HMMA, K=1024, 158 CTAs), overlapped with chain
        mma_gemm<64, 1024><<<dim3(VPAD_ / 64, 1), 256, 0, s2>>>(
            hbig + (size_t)t * B_ * 1024, Wbig, b_fc,
            out + (size_t)t * V_, (long)(T_ * V_), V_);
    }
    cudaEventRecord(evJ2, s2);                        // join s2
    cudaStreamWaitEvent(0, evJ2, 0);
}

// round 8
// speedup vs baseline: 1.2530x; 1.0833x over previous
#include <cuda_runtime.h>
#include <cuda_fp16.h>
#include <cstdint>

#define B_    128
#define T_    25
#define L_    49
#define V_    10000
#define E_    512
#define H_    512
#define ENC_  512
#define BL_   (B_ * L_)      // 6272
#define BT_   (B_ * T_)      // 3200
#define VPAD_ 10112          // 79 * 128

typedef unsigned long long ull;

// ---------------- device scratch ----------------
__device__ float g_enc_proj[BL_ * H_];
__device__ float g_gates_pre[(size_t)BT_ * 4 * H_]; // [3200][2048] permuted cols
__device__ float g_W1T[H_ * 2560];              // k-major [512][2560]: [W_h | perm(W_hh)]
__device__ float g_W2T[H_ * 2048];              // k-major [512][2048]: perm(W_ih[:,512:])
__device__ float g_bsum[4 * H_];                // permuted
__device__ float g_big1[B_ * 2560];
__device__ float g_ctxT[ENC_ * B_];
__device__ float g_hT[(T_ + 1) * H_ * B_];
__device__ float g_c[2 * B_ * H_];
// fp16 tensor-GEMM operands
__device__ __align__(16) __half g_Wbig[(size_t)VPAD_ * 1024];   // [w1 | w2]
__device__ __align__(16) __half g_hbig[(size_t)T_ * B_ * 1024]; // [h1 | h1]
__device__ __align__(16) __half g_encA[(size_t)BL_ * 512];
__device__ __align__(16) __half g_embX[(size_t)BT_ * 512];
__device__ __align__(16) __half g_WeB[(size_t)H_ * 512];
__device__ __align__(16) __half g_WihB[(size_t)(4 * H_) * 512];

// ---------------- fast transcendentals ----------------
__device__ __forceinline__ float fex2(float x) {
    float y; asm("ex2.approx.ftz.f32 %0, %1;" : "=f"(y) : "f"(x)); return y;
}
__device__ __forceinline__ float frcp(float x) {
    float y; asm("rcp.approx.ftz.f32 %0, %1;" : "=f"(y) : "f"(x)); return y;
}
__device__ __forceinline__ float ftanh_hw(float x) {
    float y; asm("tanh.approx.f32 %0, %1;" : "=f"(y) : "f"(x)); return y;
}
__device__ __forceinline__ float ftanh(float x) {
    float xc = fminf(fmaxf(x, -8.f), 8.f);
    float e = fex2(xc * 2.8853900817779268f);
    return (e - 1.f) * frcp(e + 1.f);
}
__device__ __forceinline__ float fsig(float x) {
    float xc = fminf(fmaxf(x, -30.f), 30.f);
    float e = fex2(-xc * 1.4426950408889634f);
    return frcp(1.f + e);
}

// ---------------- f32x2 helpers ----------------
__device__ __forceinline__ ull ld64s(const float* p) {
    return *reinterpret_cast<const ull*>(p);
}
__device__ __forceinline__ void fma2(ull& d, ull a, ull b) {
    asm("fma.rn.f32x2 %0, %1, %2, %0;" : "+l"(d) : "l"(a), "l"(b));
}
__device__ __forceinline__ ull pack2(float x) {
    ull r; asm("mov.b64 %0, {%1, %1};" : "=l"(r) : "f"(x)); return r;
}
__device__ __forceinline__ float lo2(ull v) { return __uint_as_float((unsigned)v); }
__device__ __forceinline__ float hi2(ull v) { return __uint_as_float((unsigned)(v >> 32)); }

// ---------------- mma.sync helpers ----------------
__device__ __forceinline__ uint32_t smem_u32(const void* p) {
    uint32_t a;
    asm("{ .reg .u64 t; cvta.to.shared.u64 t, %1; cvt.u32.u64 %0, t; }"
        : "=r"(a) : "l"(p));
    return a;
}
__device__ __forceinline__ void ldm_x4(uint32_t* r, uint32_t addr) {
    asm volatile("ldmatrix.sync.aligned.m8n8.x4.shared.b16 {%0,%1,%2,%3}, [%4];"
        : "=r"(r[0]), "=r"(r[1]), "=r"(r[2]), "=r"(r[3]) : "r"(addr));
}
__device__ __forceinline__ void mma_f16(float* d, const uint32_t* a,
                                        uint32_t b0, uint32_t b1) {
    asm volatile("mma.sync.aligned.m16n8k16.row.col.f32.f16.f16.f32 "
        "{%0,%1,%2,%3}, {%4,%5,%6,%7}, {%8,%9}, {%0,%1,%2,%3};"
        : "+f"(d[0]), "+f"(d[1]), "+f"(d[2]), "+f"(d[3])
        : "r"(a[0]), "r"(a[1]), "r"(a[2]), "r"(a[3]), "r"(b0), "r"(b1));
}
__device__ __forceinline__ void cp16(uint32_t dst, const void* src) {
    asm volatile("cp.async.cg.shared.global [%0], [%1], 16;"
                 :: "r"(dst), "l"(src));
}

#define SMEM_BYTES_ (4 * 256 * 80)   // 4 stages x (128 A + 128 B rows) x 80B

// ---------------------------------------------------------------------------
// fp16 HMMA GEMM, cp.async 4-stage pipeline.
// out[m,n] = sum_k A[m,k]*Bm[n,k] (+bias). CTA 128m x 128n, 8 warps (2m x 4n).
// ---------------------------------------------------------------------------
template<int KLEN>
__global__ void __launch_bounds__(256) mma_gemm(
    const __half* __restrict__ A,
    const __half* __restrict__ Bm,
    const float* __restrict__ bias,
    float* __restrict__ out, long ldout, int Nvalid)
{
    constexpr int NCH = KLEN / 32;
    extern __shared__ __align__(16) __half smh[];   // [4][256][40]
    const int tid = threadIdx.x;
    const int l = tid & 31, wid = tid >> 5;
    const int wm = wid >> 2, wn = wid & 3;
    const int mbase = blockIdx.y * 128;
    const int nbase = blockIdx.x * 128;
    const __half* Asrc = A + (size_t)mbase * KLEN;
    const __half* Bsrc = Bm + (size_t)nbase * KLEN;
    const uint32_t sb = smem_u32(smh);

    float d[4][4][4];
#pragma unroll
    for (int i = 0; i < 4; i++)
#pragma unroll
        for (int j = 0; j < 4; j++)
#pragma unroll
            for (int q = 0; q < 4; q++) d[i][j][q] = 0.f;

    const int arow = wm * 64 + (l & 15);
    const int acol = (l >> 4) * 8;
    const int brow = wn * 32 + ((l >> 4) << 3) + (l & 7);
    const int bcol = ((l >> 3) & 1) * 8;

    // per-thread fixed load slot: 4 x 16B per chunk
    const int lr = tid >> 2;          // row 0..63 step: +64 per q
    const int lc = (tid & 3) * 8;     // half offset within 32-half chunk row

    auto issue_chunk = [&](int c, int buf) {
        const uint32_t dbase = sb + buf * 20480;
#pragma unroll
        for (int q = 0; q < 4; q++) {
            int r = lr + q * 64;
            const __half* s = (r < 128) ? (Asrc + (size_t)r * KLEN)
                                        : (Bsrc + (size_t)(r - 128) * KLEN);
            cp16(dbase + r * 80 + lc * 2, s + c * 32 + lc);
        }
        asm volatile("cp.async.commit_group;" ::: "memory");
    };

    issue_chunk(0, 0);
    issue_chunk(1, 1);
    issue_chunk(2, 2);

#pragma unroll 1
    for (int c = 0; c < NCH; c++) {
        if (c + 3 < NCH) asm volatile("cp.async.wait_group 2;" ::: "memory");
        else             asm volatile("cp.async.wait_group 0;" ::: "memory");
        __syncthreads();
        if (c + 3 < NCH) issue_chunk(c + 3, (c + 3) & 3);
        const uint32_t base = sb + (c & 3) * 20480;
#pragma unroll
        for (int s = 0; s < 2; s++) {
            uint32_t ar[4][4];
#pragma unroll
            for (int fm = 0; fm < 4; fm++)
                ldm_x4(ar[fm],
                       base + ((arow + fm * 16) * 40 + acol + s * 16) * 2);
#pragma unroll
            for (int fp = 0; fp < 2; fp++) {
                uint32_t br[4];
                ldm_x4(br, base + 128 * 80 +
                           ((brow + fp * 16) * 40 + bcol + s * 16) * 2);
#pragma unroll
                for (int fm = 0; fm < 4; fm++) {
                    mma_f16(d[fm][fp * 2],     ar[fm], br[0], br[1]);
                    mma_f16(d[fm][fp * 2 + 1], ar[fm], br[2], br[3]);
                }
            }
        }
    }

#pragma unroll
    for (int fm = 0; fm < 4; fm++) {
        int m0 = mbase + wm * 64 + fm * 16 + (l >> 2);
#pragma unroll
        for (int fn = 0; fn < 4; fn++) {
            int n0 = nbase + wn * 32 + fn * 8 + (l & 3) * 2;
            if (n0 < Nvalid) {
                float b0 = bias ? bias[n0] : 0.f;
                float b1 = bias ? bias[n0 + 1] : 0.f;
                float2 v0 = make_float2(d[fm][fn][0] + b0, d[fm][fn][1] + b1);
                float2 v1 = make_float2(d[fm][fn][2] + b0, d[fm][fn][3] + b1);
                *(float2*)&out[(size_t)m0 * ldout + n0] = v0;
                *(float2*)&out[(size_t)(m0 + 8) * ldout + n0] = v1;
            }
        }
    }
}

// ---------------------------------------------------------------------------
// f32x2 GEMM core: 64m x 32n CTA tile, K=512, k-major operands (mstride=128).
// ---------------------------------------------------------------------------
__device__ __forceinline__ void gemm64_core(
    const float* __restrict__ XT, const float* __restrict__ WT, int nstride,
    float (*Xs)[64], float (*Ws)[32], int mbase, int nb, ull acc[2][2])
{
    const int tid = threadIdx.x;
    const int tx = tid & 15, ty = tid >> 4;
    acc[0][0] = acc[0][1] = acc[1][0] = acc[1][1] = 0ull;
    const int kx = tid >> 4, mw = (tid & 15) << 2;
    const int nw = (tid & 15) << 1;
#pragma unroll 1
    for (int k0 = 0; k0 < 512; k0 += 16) {
        *(float4*)&Xs[kx][mw] = *(const float4*)(XT + (k0 + kx) * 128 + mbase + mw);
        *(float2*)&Ws[kx][nw] = *(const float2*)(WT + (size_t)(k0 + kx) * nstride + nb + nw);
        __syncthreads();
#pragma unroll
        for (int kk = 0; kk < 16; kk++) {
            ull a0 = ld64s(&Xs[kk][ty * 4]);
            ull a1 = ld64s(&Xs[kk][ty * 4 + 2]);
            float2 bw = *(const float2*)&Ws[kk][tx * 2];
            ull b0 = pack2(bw.x), b1 = pack2(bw.y);
            fma2(acc[0][0], a0, b0);
            fma2(acc[0][1], a0, b1);
            fma2(acc[1][0], a1, b0);
            fma2(acc[1][1], a1, b1);
        }
        __syncthreads();
    }
}

// GEMM1: big1[b][0:2560] = h(t) @ [W_h | perm(W_hh)]^T.  grid(80, 2)
__global__ void __launch_bounds__(256) gemm1_k(const float* __restrict__ hTt) {
    __shared__ float Xs[16][64];
    __shared__ float Ws[16][32];
    const int nb = blockIdx.x * 32, mbase = blockIdx.y * 64;
    ull acc[2][2];
    gemm64_core(hTt, g_W1T, 2560, Xs, Ws, mbase, nb, acc);
    const int tx = threadIdx.x & 15, ty = threadIdx.x >> 4;
#pragma unroll
    for (int p = 0; p < 2; p++) {
        int m = mbase + ty * 4 + p * 2;
#pragma unroll
        for (int j = 0; j < 2; j++) {
            int n = nb + tx * 2 + j;
            g_big1[m * 2560 + n]       = lo2(acc[p][j]);
            g_big1[(m + 1) * 2560 + n] = hi2(acc[p][j]);
        }
    }
}

// GEMM2 + LSTM pointwise fused.  grid(64, 2)
__global__ void __launch_bounds__(256) gemm2_lstm(int t) {
    __shared__ float Xs[16][64];
    __shared__ float Ws[16][32];
    __shared__ float gs[64][33];
    const int nb = blockIdx.x * 32, mbase = blockIdx.y * 64;
    ull acc[2][2];
    gemm64_core(g_ctxT, g_W2T, 2048, Xs, Ws, mbase, nb, acc);

    const int tid = threadIdx.x;
    const int tx = tid & 15, ty = tid >> 4;
#pragma unroll
    for (int p = 0; p < 2; p++) {
        int bl = ty * 4 + p * 2;
        int b = mbase + bl;
#pragma unroll
        for (int j = 0; j < 2; j++) {
            int ln = tx * 2 + j;
            int n = nb + ln;
            gs[bl][ln] = lo2(acc[p][j]) + g_big1[b * 2560 + 512 + n]
                       + g_gates_pre[((size_t)(t * B_ + b)) * 2048 + n];
            gs[bl + 1][ln] = hi2(acc[p][j]) + g_big1[(b + 1) * 2560 + 512 + n]
                       + g_gates_pre[((size_t)(t * B_ + b + 1)) * 2048 + n];
        }
    }
    __syncthreads();

#pragma unroll
    for (int q = 0; q < 2; q++) {
        int idx = tid + q * 256;
        int bl = idx >> 3, ul = idx & 7;
        int b = mbase + bl;
        int u = (nb >> 2) + ul;
        float gi = gs[bl][ul * 4 + 0];
        float gf = gs[bl][ul * 4 + 1];
        float gg = gs[bl][ul * 4 + 2];
        float go = gs[bl][ul * 4 + 3];
        float cn = fsig(gf) * g_c[(size_t)(t & 1) * (B_ * H_) + b * H_ + u]
                 + fsig(gi) * ftanh(gg);
        g_c[(size_t)((t + 1) & 1) * (B_ * H_) + b * H_ + u] = cn;
        float h = fsig(go) * ftanh(cn);
        g_hT[(size_t)(t + 1) * (H_ * B_) + (size_t)u * B_ + b] = h;
        __half h1 = __float2half_rn(h);
        __half* row = g_hbig + ((size_t)t * B_ + b) * 1024;
        row[u]       = h1;
        row[512 + u] = h1;
    }
}

// ---------------------------------------------------------------------------
__global__ void __launch_bounds__(512) attn_kernel(
    const float* __restrict__ enc, const float* __restrict__ vattn) {
    const int b = blockIdx.x, tid = threadIdx.x;
    __shared__ float hp_s[H_];
    __shared__ float v_s[H_];
    __shared__ float sc[64];

    hp_s[tid] = g_big1[b * 2560 + tid];
    v_s[tid] = vattn[tid];
    __syncthreads();

    const int w = tid >> 5, lane = tid & 31;
    const float* ep = g_enc_proj + (size_t)b * L_ * H_;
    for (int l = w; l < L_; l += 16) {
        const float* row = ep + l * H_;
        float p = 0.f;
#pragma unroll
        for (int k = lane; k < H_; k += 32)
            p += ftanh_hw(hp_s[k] + row[k]) * v_s[k];
#pragma unroll
        for (int o = 16; o; o >>= 1) p += __shfl_xor_sync(0xffffffffu, p, o);
        if (lane == 0) sc[l] = p;
    }
    __syncthreads();

    if (tid < 32) {
        float v0 = sc[tid];
        float v1 = (tid < L_ - 32) ? sc[32 + tid] : -1e30f;
        float mx = fmaxf(v0, v1);
#pragma unroll
        for (int o = 16; o; o >>= 1) mx = fmaxf(mx, __shfl_xor_sync(0xffffffffu, mx, o));
        float e0 = fex2((v0 - mx) * 1.4426950408889634f);
        float e1 = (tid < L_ - 32) ? fex2((v1 - mx) * 1.4426950408889634f) : 0.f;
        float s = e0 + e1;
#pragma unroll
        for (int o = 16; o; o >>= 1) s += __shfl_xor_sync(0xffffffffu, s, o);
        float r = frcp(s);
        sc[tid] = e0 * r;
        if (tid < L_ - 32) sc[32 + tid] = e1 * r;
    }
    __syncthreads();

    const float* eb = enc + (size_t)b * L_ * ENC_;
    float a = 0.f;
#pragma unroll 7
    for (int l = 0; l < L_; l++) a += sc[l] * eb[l * ENC_ + tid];
    g_ctxT[(size_t)tid * B_ + b] = a;
}

// ---------------------------------------------------------------------------
// preamble kernels
// ---------------------------------------------------------------------------
__global__ void transp(const float* __restrict__ in, float* __restrict__ out,
                       int R, int C, int istride, int ostride) {
    __shared__ float t[32][33];
    int c0 = blockIdx.x * 32, r0 = blockIdx.y * 32;
#pragma unroll
    for (int i = threadIdx.y; i < 32; i += 8) {
        int r = r0 + i, c = c0 + threadIdx.x;
        t[i][threadIdx.x] = (r < R && c < C) ? in[(size_t)r * istride + c] : 0.f;
    }
    __syncthreads();
#pragma unroll
    for (int i = threadIdx.y; i < 32; i += 8) {
        int c = c0 + i, r = r0 + threadIdx.x;
        if (c < C && r < R) out[(size_t)c * ostride + r] = t[threadIdx.x][i];
    }
}

__global__ void transp_pg(const float* __restrict__ in, float* __restrict__ out,
                          int in_ld, int col_off, int out_ld) {
    __shared__ float t[32][33];
    int c0 = blockIdx.x * 32, r0 = blockIdx.y * 32;
#pragma unroll
    for (int i = threadIdx.y; i < 32; i += 8)
        t[i][threadIdx.x] = in[(size_t)(r0 + i) * in_ld + col_off + c0 + threadIdx.x];
    __syncthreads();
#pragma unroll
    for (int i = threadIdx.y; i < 32; i += 8) {
        int k = c0 + i;
        int r = r0 + threadIdx.x;
        int n = ((r & 511) << 2) | (r >> 9);
        out[(size_t)k * out_ld + n] = t[threadIdx.x][i];
    }
}

__global__ void bias_sum_perm(const float* __restrict__ bi,
                              const float* __restrict__ bh) {
    int n = blockIdx.x * 256 + threadIdx.x;
    int o = ((n & 3) << 9) | (n >> 2);
    g_bsum[n] = bi[o] + bh[o];
}

__global__ void wfc_split(const float* __restrict__ W_fc) {
    int n = blockIdx.x, j = threadIdx.x;
    float w = (n < V_) ? W_fc[(size_t)n * H_ + j] : 0.f;
    __half w1 = __float2half_rn(w);
    float lo = w - __half2float(w1);
    __half* row = g_Wbig + (size_t)n * 1024;
    row[j] = w1;
    row[512 + j] = __float2half_rn(lo);
}

__global__ void h16_conv(const float* __restrict__ src, __half* __restrict__ dst) {
    int m = blockIdx.x, j = threadIdx.x;
    dst[(size_t)m * 512 + j] = __float2half_rn(src[(size_t)m * 512 + j]);
}

__global__ void wih_emb_conv(const float* __restrict__ W_ih) {
    int n = blockIdx.x, j = threadIdx.x;
    int o = ((n & 3) << 9) | (n >> 2);
    g_WihB[(size_t)n * 512 + j] = __float2half_rn(W_ih[(size_t)o * 1024 + j]);
}

__global__ void emb_gather(const int* __restrict__ cap, const float* __restrict__ emb) {
    int m = blockIdx.x;
    int b = m & 127, t = m >> 7;
    int w = cap[b * T_ + t];
    int j = threadIdx.x;
    g_embX[(size_t)m * 512 + j] = __float2half_rn(emb[(size_t)w * E_ + j]);
}

__global__ void zero_state() {
    int i = blockIdx.x * 256 + threadIdx.x;
    g_hT[i] = 0.f;
    g_c[i] = 0.f;
}

// ---------------------------------------------------------------------------
extern "C" void kernel_launch(void* const* d_in, const int* in_sizes, int n_in,
                              void* d_out, int out_size) {
    const int*   captions = (const int*)d_in[0];
    const float* enc      = (const float*)d_in[1];
    const float* emb      = (const float*)d_in[2];
    const float* W_h      = (const float*)d_in[3];
    const float* W_e      = (const float*)d_in[4];
    const float* v_attn   = (const float*)d_in[5];
    const float* W_ih     = (const float*)d_in[6];
    const float* W_hh     = (const float*)d_in[7];
    const float* b_ih     = (const float*)d_in[8];
    const float* b_hh     = (const float*)d_in[9];
    const float* W_fc     = (const float*)d_in[10];
    const float* b_fc     = (const float*)d_in[11];
    float* out = (float*)d_out;

    static cudaStream_t s2 = nullptr, s3 = nullptr, s4 = nullptr;
    static cudaEvent_t evStart = nullptr, evG = nullptr, evH = nullptr,
                       evW = nullptr, evJ2 = nullptr, evJ4 = nullptr;
    if (!s2) {
        cudaStreamCreateWithFlags(&s2, cudaStreamNonBlocking);
        cudaStreamCreateWithFlags(&s3, cudaStreamNonBlocking);
        cudaStreamCreateWithFlags(&s4, cudaStreamNonBlocking);
        cudaEventCreateWithFlags(&evStart, cudaEventDisableTiming);
        cudaEventCreateWithFlags(&evG,  cudaEventDisableTiming);
        cudaEventCreateWithFlags(&evH,  cudaEventDisableTiming);
        cudaEventCreateWithFlags(&evW,  cudaEventDisableTiming);
        cudaEventCreateWithFlags(&evJ2, cudaEventDisableTiming);
        cudaEventCreateWithFlags(&evJ4, cudaEventDisableTiming);
    }
    cudaFuncSetAttribute(mma_gemm<1024>,
                         cudaFuncAttributeMaxDynamicSharedMemorySize, SMEM_BYTES_);
    cudaFuncSetAttribute(mma_gemm<512>,
                         cudaFuncAttributeMaxDynamicSharedMemorySize, SMEM_BYTES_);

    float *enc_proj, *gates_pre, *W1T, *W2T, *bsum, *hT;
    __half *Wbig, *hbig, *encA, *embX, *WeB, *WihB;
    cudaGetSymbolAddress((void**)&enc_proj,  g_enc_proj);
    cudaGetSymbolAddress((void**)&gates_pre, g_gates_pre);
    cudaGetSymbolAddress((void**)&W1T,       g_W1T);
    cudaGetSymbolAddress((void**)&W2T,       g_W2T);
    cudaGetSymbolAddress((void**)&bsum,      g_bsum);
    cudaGetSymbolAddress((void**)&hT,        g_hT);
    cudaGetSymbolAddress((void**)&Wbig,      g_Wbig);
    cudaGetSymbolAddress((void**)&hbig,      g_hbig);
    cudaGetSymbolAddress((void**)&encA,      g_encA);
    cudaGetSymbolAddress((void**)&embX,      g_embX);
    cudaGetSymbolAddress((void**)&WeB,       g_WeB);
    cudaGetSymbolAddress((void**)&WihB,      g_WihB);

    const dim3 tb(32, 8);

    // fork: all side streams join the capture BEFORE any of their work
    zero_state<<<256, 256>>>();
    cudaEventRecord(evStart, 0);
    cudaStreamWaitEvent(s2, evStart, 0);
    cudaStreamWaitEvent(s3, evStart, 0);
    cudaStreamWaitEvent(s4, evStart, 0);

    // s2: W_fc 2-term split (feeds logits on both logits streams)
    wfc_split<<<VPAD_, 512, 0, s2>>>(W_fc);
    cudaEventRecord(evW, s2);
    cudaStreamWaitEvent(s4, evW, 0);

    // s3: gates_pre pipeline (fp16 single-term, permuted columns)
    bias_sum_perm<<<8, 256, 0, s3>>>(b_ih, b_hh);
    emb_gather<<<BT_, 512, 0, s3>>>(captions, emb);
    wih_emb_conv<<<4 * H_, 512, 0, s3>>>(W_ih);
    mma_gemm<512><<<dim3(16, T_), 256, SMEM_BYTES_, s3>>>(
        embX, WihB, bsum, gates_pre, 4L * H_, 4 * H_);
    cudaEventRecord(evG, s3);

    // s1: chain weights + enc_proj
    transp<<<dim3(16, 16), tb>>>(W_h, W1T, H_, H_, H_, 2560);
    transp_pg<<<dim3(16, 64), tb>>>(W_hh, W1T + 512, 512, 0, 2560);
    transp_pg<<<dim3(16, 64), tb>>>(W_ih, W2T, 1024, 512, 2048);
    h16_conv<<<H_, 512>>>(W_e, WeB);
    h16_conv<<<BL_, 512>>>(enc, encA);
    mma_gemm<512><<<dim3(4, BL_ / 128), 256, SMEM_BYTES_>>>(
        encA, WeB, nullptr, enc_proj, (long)H_, H_);

    cudaStream_t sL[2] = {s2, s4};
    for (int t = 0; t < T_; t++) {
        gemm1_k<<<dim3(80, 2), 256>>>(hT + (size_t)t * H_ * B_);
        attn_kernel<<<B_, 512>>>(enc, v_attn);
        if (t == 0) cudaStreamWaitEvent(0, evG, 0);   // join s3 (gates_pre)
        gemm2_lstm<<<dim3(64, 2), 256>>>(t);
        cudaEventRecord(evH, 0);
        cudaStreamWaitEvent(sL[t & 1], evH, 0);
        // logits: fp16 HMMA K=1024, 79 CTAs, alternating streams
        mma_gemm<1024><<<dim3(79, 1), 256, SMEM_BYTES_, sL[t & 1]>>>(
            hbig + (size_t)t * B_ * 1024, Wbig, b_fc,
            out + (size_t)t * V_, (long)(T_ * V_), V_);
    }
    cudaEventRecord(evJ2, s2);
    cudaStreamWaitEvent(0, evJ2, 0);
    cudaEventRecord(evJ4, s4);
    cudaStreamWaitEvent(0, evJ4, 0);
}

// round 9
// speedup vs baseline: 1.9384x; 1.5469x over previous
#include <cuda_runtime.h>
#include <cuda_fp16.h>
#include <cstdint>

#define B_    128
#define T_    25
#define L_    49
#define V_    10000
#define E_    512
#define H_    512
#define ENC_  512
#define BL_   (B_ * L_)      // 6272
#define BT_   (B_ * T_)      // 3200
#define VPAD_ 10112          // 79 * 128

typedef unsigned long long ull;

// ---------------- device scratch ----------------
__device__ float g_enc_proj[BL_ * H_];              // [6272][512]
__device__ float g_gates_pre[(size_t)BT_ * 4 * H_]; // [3200][2048] permuted cols
__device__ float g_bsum[4 * H_];                    // permuted
__device__ float g_big1[B_ * 2560];                 // [128][hp(512)|gates_h(2048)]
__device__ float g_c[2 * B_ * H_];
// fp16 HMMA operands (all single-term, row-major [N][512])
__device__ __align__(16) __half g_Wbig[(size_t)VPAD_ * 512];        // w1(W_fc)
__device__ __align__(16) __half g_hbig[(size_t)(T_ + 1) * B_ * 512];// slot t = h(t)
__device__ __align__(16) __half g_W1H[2560 * 512];  // [W_h | perm(W_hh)]
__device__ __align__(16) __half g_W2H[2048 * 512];  // perm(W_ih[:,512:])
__device__ __align__(16) __half g_ctxH[B_ * 512];   // ctx fp16 row-major
__device__ __align__(16) __half g_encA[(size_t)BL_ * 512];
__device__ __align__(16) __half g_embX[(size_t)BT_ * 512];
__device__ __align__(16) __half g_WeB[(size_t)H_ * 512];
__device__ __align__(16) __half g_WihB[(size_t)(4 * H_) * 512];

// ---------------- fast transcendentals ----------------
__device__ __forceinline__ float fex2(float x) {
    float y; asm("ex2.approx.ftz.f32 %0, %1;" : "=f"(y) : "f"(x)); return y;
}
__device__ __forceinline__ float frcp(float x) {
    float y; asm("rcp.approx.ftz.f32 %0, %1;" : "=f"(y) : "f"(x)); return y;
}
__device__ __forceinline__ float ftanh_hw(float x) {
    float y; asm("tanh.approx.f32 %0, %1;" : "=f"(y) : "f"(x)); return y;
}
__device__ __forceinline__ float ftanh(float x) {
    float xc = fminf(fmaxf(x, -8.f), 8.f);
    float e = fex2(xc * 2.8853900817779268f);
    return (e - 1.f) * frcp(e + 1.f);
}
__device__ __forceinline__ float fsig(float x) {
    float xc = fminf(fmaxf(x, -30.f), 30.f);
    float e = fex2(-xc * 1.4426950408889634f);
    return frcp(1.f + e);
}

// ---------------- mma.sync helpers ----------------
__device__ __forceinline__ uint32_t smem_u32(const void* p) {
    uint32_t a;
    asm("{ .reg .u64 t; cvta.to.shared.u64 t, %1; cvt.u32.u64 %0, t; }"
        : "=r"(a) : "l"(p));
    return a;
}
__device__ __forceinline__ void ldm_x4(uint32_t* r, uint32_t addr) {
    asm volatile("ldmatrix.sync.aligned.m8n8.x4.shared.b16 {%0,%1,%2,%3}, [%4];"
        : "=r"(r[0]), "=r"(r[1]), "=r"(r[2]), "=r"(r[3]) : "r"(addr));
}
__device__ __forceinline__ void mma_f16(float* d, const uint32_t* a,
                                        uint32_t b0, uint32_t b1) {
    asm volatile("mma.sync.aligned.m16n8k16.row.col.f32.f16.f16.f32 "
        "{%0,%1,%2,%3}, {%4,%5,%6,%7}, {%8,%9}, {%0,%1,%2,%3};"
        : "+f"(d[0]), "+f"(d[1]), "+f"(d[2]), "+f"(d[3])
        : "r"(a[0]), "r"(a[1]), "r"(a[2]), "r"(a[3]), "r"(b0), "r"(b1));
}
__device__ __forceinline__ void cp16(uint32_t dst, const void* src) {
    asm volatile("cp.async.cg.shared.global [%0], [%1], 16;"
                 :: "r"(dst), "l"(src));
}

#define SMEM_BYTES_ (4 * 256 * 80)   // 4 stages x (128 A + 128 B rows) x 80B
#define KLEN_ 512
#define NCH_  16

// ---------------------------------------------------------------------------
// Shared HMMA mainloop: CTA 128m x 128n, K=512, 8 warps (2m x 4n),
// cp.async 4-stage pipeline. Leaves results in d[4][4][4].
// ---------------------------------------------------------------------------
struct MmaCtx {
    float d[4][4][4];
    int arow, acol, brow, bcol, l, wm, wn;
    uint32_t sb;
};

__device__ __forceinline__ void mma_mainloop(
    MmaCtx& cx, const __half* Asrc, const __half* Bsrc, __half* smh)
{
    const int tid = threadIdx.x;
    const int l = tid & 31, wid = tid >> 5;
    cx.l = l; cx.wm = wid >> 2; cx.wn = wid & 3;
    cx.sb = smem_u32(smh);
#pragma unroll
    for (int i = 0; i < 4; i++)
#pragma unroll
        for (int j = 0; j < 4; j++)
#pragma unroll
            for (int q = 0; q < 4; q++) cx.d[i][j][q] = 0.f;

    cx.arow = cx.wm * 64 + (l & 15);
    cx.acol = (l >> 4) * 8;
    cx.brow = cx.wn * 32 + ((l >> 4) << 3) + (l & 7);
    cx.bcol = ((l >> 3) & 1) * 8;

    const int lr = tid >> 2;
    const int lc = (tid & 3) * 8;

    auto issue_chunk = [&](int c, int buf) {
        const uint32_t dbase = cx.sb + buf * 20480;
#pragma unroll
        for (int q = 0; q < 4; q++) {
            int r = lr + q * 64;
            const __half* s = (r < 128) ? (Asrc + (size_t)r * KLEN_)
                                        : (Bsrc + (size_t)(r - 128) * KLEN_);
            cp16(dbase + r * 80 + lc * 2, s + c * 32 + lc);
        }
        asm volatile("cp.async.commit_group;" ::: "memory");
    };

    issue_chunk(0, 0);
    issue_chunk(1, 1);
    issue_chunk(2, 2);

#pragma unroll 1
    for (int c = 0; c < NCH_; c++) {
        if (c + 3 < NCH_) asm volatile("cp.async.wait_group 2;" ::: "memory");
        else              asm volatile("cp.async.wait_group 0;" ::: "memory");
        __syncthreads();
        if (c + 3 < NCH_) issue_chunk(c + 3, (c + 3) & 3);
        const uint32_t base = cx.sb + (c & 3) * 20480;
#pragma unroll
        for (int s = 0; s < 2; s++) {
            uint32_t ar[4][4];
#pragma unroll
            for (int fm = 0; fm < 4; fm++)
                ldm_x4(ar[fm],
                       base + ((cx.arow + fm * 16) * 40 + cx.acol + s * 16) * 2);
#pragma unroll
            for (int fp = 0; fp < 2; fp++) {
                uint32_t br[4];
                ldm_x4(br, base + 128 * 80 +
                           ((cx.brow + fp * 16) * 40 + cx.bcol + s * 16) * 2);
#pragma unroll
                for (int fm = 0; fm < 4; fm++) {
                    mma_f16(cx.d[fm][fp * 2],     ar[fm], br[0], br[1]);
                    mma_f16(cx.d[fm][fp * 2 + 1], ar[fm], br[2], br[3]);
                }
            }
        }
    }
}

// ---------------------------------------------------------------------------
// Generic GEMM with fp32 output (+optional bias): logits, enc_proj,
// gates_pre, gemm1.  grid(N/128, M/128).
// ---------------------------------------------------------------------------
__global__ void __launch_bounds__(256) mma_gemm(
    const __half* __restrict__ A, const __half* __restrict__ Bm,
    const float* __restrict__ bias, float* __restrict__ out,
    long ldout, int Nvalid)
{
    extern __shared__ __align__(16) __half smh[];
    const int mbase = blockIdx.y * 128;
    const int nbase = blockIdx.x * 128;
    MmaCtx cx;
    mma_mainloop(cx, A + (size_t)mbase * KLEN_, Bm + (size_t)nbase * KLEN_, smh);

#pragma unroll
    for (int fm = 0; fm < 4; fm++) {
        int m0 = mbase + cx.wm * 64 + fm * 16 + (cx.l >> 2);
#pragma unroll
        for (int fn = 0; fn < 4; fn++) {
            int n0 = nbase + cx.wn * 32 + fn * 8 + (cx.l & 3) * 2;
            if (n0 < Nvalid) {
                float b0 = bias ? bias[n0] : 0.f;
                float b1 = bias ? bias[n0 + 1] : 0.f;
                float2 v0 = make_float2(cx.d[fm][fn][0] + b0, cx.d[fm][fn][1] + b1);
                float2 v1 = make_float2(cx.d[fm][fn][2] + b0, cx.d[fm][fn][3] + b1);
                *(float2*)&out[(size_t)m0 * ldout + n0] = v0;
                *(float2*)&out[(size_t)(m0 + 8) * ldout + n0] = v1;
            }
        }
    }
}

// ---------------------------------------------------------------------------
// gemm2 + LSTM pointwise fused: gates tile = ctx@W2^T + big1_gatesh +
// gates_pre, then c/h update.  grid(16, 1): nbase = bx*128 gate-cols.
// ---------------------------------------------------------------------------
__global__ void __launch_bounds__(256) gemm2_lstm(int t) {
    extern __shared__ __align__(16) __half smh[];
    const int nbase = blockIdx.x * 128;
    MmaCtx cx;
    mma_mainloop(cx, g_ctxH, g_W2H + (size_t)nbase * KLEN_, smh);

    __syncthreads();                        // pipeline smem -> gates smem reuse
    float* gsm = reinterpret_cast<float*>(smh);   // [128][130]
#pragma unroll
    for (int fm = 0; fm < 4; fm++) {
        int m0 = cx.wm * 64 + fm * 16 + (cx.l >> 2);
#pragma unroll
        for (int fn = 0; fn < 4; fn++) {
            int n0 = cx.wn * 32 + fn * 8 + (cx.l & 3) * 2;
#pragma unroll
            for (int hh = 0; hh < 2; hh++) {
                int m = m0 + hh * 8;
                const float* pre =
                    &g_gates_pre[((size_t)(t * B_ + m)) * 2048 + nbase + n0];
                const float* bh = &g_big1[m * 2560 + 512 + nbase + n0];
                gsm[m * 130 + n0]     = cx.d[fm][fn][hh * 2]     + bh[0] + pre[0];
                gsm[m * 130 + n0 + 1] = cx.d[fm][fn][hh * 2 + 1] + bh[1] + pre[1];
            }
        }
    }
    __syncthreads();

    const int tid = threadIdx.x;
#pragma unroll
    for (int q = 0; q < 16; q++) {
        int idx = tid + q * 256;
        int b = idx >> 5, ul = idx & 31;    // 128 b x 32 units
        int u = (nbase >> 2) + ul;
        float gi = gsm[b * 130 + ul * 4 + 0];
        float gf = gsm[b * 130 + ul * 4 + 1];
        float gg = gsm[b * 130 + ul * 4 + 2];
        float go = gsm[b * 130 + ul * 4 + 3];
        float cn = fsig(gf) * g_c[(size_t)(t & 1) * (B_ * H_) + b * H_ + u]
                 + fsig(gi) * ftanh(gg);
        g_c[(size_t)((t + 1) & 1) * (B_ * H_) + b * H_ + u] = cn;
        float h = fsig(go) * ftanh(cn);
        g_hbig[(size_t)(t + 1) * (B_ * 512) + b * 512 + u] = __float2half_rn(h);
    }
}

// ---------------------------------------------------------------------------
// Attention: hp from big1[:, 0:512]; scores; softmax; ctx -> ctxH fp16.
// ---------------------------------------------------------------------------
__global__ void __launch_bounds__(512) attn_kernel(
    const float* __restrict__ enc, const float* __restrict__ vattn) {
    const int b = blockIdx.x, tid = threadIdx.x;
    __shared__ float hp_s[H_];
    __shared__ float v_s[H_];
    __shared__ float sc[64];

    hp_s[tid] = g_big1[b * 2560 + tid];
    v_s[tid] = vattn[tid];
    __syncthreads();

    const int w = tid >> 5, lane = tid & 31;
    const float* ep = g_enc_proj + (size_t)b * L_ * H_;
    for (int l = w; l < L_; l += 16) {
        const float* row = ep + l * H_;
        float p = 0.f;
#pragma unroll
        for (int k = lane; k < H_; k += 32)
            p += ftanh_hw(hp_s[k] + row[k]) * v_s[k];
#pragma unroll
        for (int o = 16; o; o >>= 1) p += __shfl_xor_sync(0xffffffffu, p, o);
        if (lane == 0) sc[l] = p;
    }
    __syncthreads();

    if (tid < 32) {
        float v0 = sc[tid];
        float v1 = (tid < L_ - 32) ? sc[32 + tid] : -1e30f;
        float mx = fmaxf(v0, v1);
#pragma unroll
        for (int o = 16; o; o >>= 1) mx = fmaxf(mx, __shfl_xor_sync(0xffffffffu, mx, o));
        float e0 = fex2((v0 - mx) * 1.4426950408889634f);
        float e1 = (tid < L_ - 32) ? fex2((v1 - mx) * 1.4426950408889634f) : 0.f;
        float s = e0 + e1;
#pragma unroll
        for (int o = 16; o; o >>= 1) s += __shfl_xor_sync(0xffffffffu, s, o);
        float r = frcp(s);
        sc[tid] = e0 * r;
        if (tid < L_ - 32) sc[32 + tid] = e1 * r;
    }
    __syncthreads();

    const float* eb = enc + (size_t)b * L_ * ENC_;
    float a = 0.f;
#pragma unroll 7
    for (int l = 0; l < L_; l++) a += sc[l] * eb[l * ENC_ + tid];
    g_ctxH[b * 512 + tid] = __float2half_rn(a);
}

// ---------------------------------------------------------------------------
// preamble kernels (fp16 converts)
// ---------------------------------------------------------------------------
__global__ void bias_sum_perm(const float* __restrict__ bi,
                              const float* __restrict__ bh) {
    int n = blockIdx.x * 256 + threadIdx.x;
    int o = ((n & 3) << 9) | (n >> 2);
    g_bsum[n] = bi[o] + bh[o];
}

__global__ void wfc_conv(const float* __restrict__ W_fc) {
    int n = blockIdx.x, j = threadIdx.x;
    float w = (n < V_) ? W_fc[(size_t)n * H_ + j] : 0.f;
    g_Wbig[(size_t)n * 512 + j] = __float2half_rn(w);
}

__global__ void w1h_conv(const float* __restrict__ W_h,
                         const float* __restrict__ W_hh) {
    int n = blockIdx.x, j = threadIdx.x;
    float w;
    if (n < 512) w = W_h[(size_t)n * H_ + j];
    else {
        int p = n - 512;
        int o = ((p & 3) << 9) | (p >> 2);
        w = W_hh[(size_t)o * H_ + j];
    }
    g_W1H[(size_t)n * 512 + j] = __float2half_rn(w);
}

__global__ void w2_conv(const float* __restrict__ W_ih) {
    int n = blockIdx.x, j = threadIdx.x;
    int o = ((n & 3) << 9) | (n >> 2);
    g_W2H[(size_t)n * 512 + j] = __float2half_rn(W_ih[(size_t)o * 1024 + 512 + j]);
}

__global__ void wih_emb_conv(const float* __restrict__ W_ih) {
    int n = blockIdx.x, j = threadIdx.x;
    int o = ((n & 3) << 9) | (n >> 2);
    g_WihB[(size_t)n * 512 + j] = __float2half_rn(W_ih[(size_t)o * 1024 + j]);
}

__global__ void h16_conv(const float* __restrict__ src, __half* __restrict__ dst) {
    int m = blockIdx.x, j = threadIdx.x;
    dst[(size_t)m * 512 + j] = __float2half_rn(src[(size_t)m * 512 + j]);
}

__global__ void emb_gather(const int* __restrict__ cap, const float* __restrict__ emb) {
    int m = blockIdx.x;
    int b = m & 127, t = m >> 7;
    int w = cap[b * T_ + t];
    int j = threadIdx.x;
    g_embX[(size_t)m * 512 + j] = __float2half_rn(emb[(size_t)w * E_ + j]);
}

__global__ void zero_state() {
    int i = blockIdx.x * 256 + threadIdx.x;   // 65536
    g_hbig[i] = __float2half_rn(0.f);         // slot 0 = h(0) = 0
    g_c[i] = 0.f;                             // parity 0
}

// ---------------------------------------------------------------------------
extern "C" void kernel_launch(void* const* d_in, const int* in_sizes, int n_in,
                              void* d_out, int out_size) {
    const int*   captions = (const int*)d_in[0];
    const float* enc      = (const float*)d_in[1];
    const float* emb      = (const float*)d_in[2];
    const float* W_h      = (const float*)d_in[3];
    const float* W_e      = (const float*)d_in[4];
    const float* v_attn   = (const float*)d_in[5];
    const float* W_ih     = (const float*)d_in[6];
    const float* W_hh     = (const float*)d_in[7];
    const float* b_ih     = (const float*)d_in[8];
    const float* b_hh     = (const float*)d_in[9];
    const float* W_fc     = (const float*)d_in[10];
    const float* b_fc     = (const float*)d_in[11];
    float* out = (float*)d_out;

    static cudaStream_t s2 = nullptr, s3 = nullptr, s4 = nullptr;
    static cudaEvent_t evStart = nullptr, evG = nullptr, evH = nullptr,
                       evW = nullptr, evJ2 = nullptr, evJ4 = nullptr;
    if (!s2) {
        cudaStreamCreateWithFlags(&s2, cudaStreamNonBlocking);
        cudaStreamCreateWithFlags(&s3, cudaStreamNonBlocking);
        cudaStreamCreateWithFlags(&s4, cudaStreamNonBlocking);
        cudaEventCreateWithFlags(&evStart, cudaEventDisableTiming);
        cudaEventCreateWithFlags(&evG,  cudaEventDisableTiming);
        cudaEventCreateWithFlags(&evH,  cudaEventDisableTiming);
        cudaEventCreateWithFlags(&evW,  cudaEventDisableTiming);
        cudaEventCreateWithFlags(&evJ2, cudaEventDisableTiming);
        cudaEventCreateWithFlags(&evJ4, cudaEventDisableTiming);
    }
    cudaFuncSetAttribute(mma_gemm,
                         cudaFuncAttributeMaxDynamicSharedMemorySize, SMEM_BYTES_);
    cudaFuncSetAttribute(gemm2_lstm,
                         cudaFuncAttributeMaxDynamicSharedMemorySize, SMEM_BYTES_);

    float *enc_proj, *gates_pre, *bsum;
    __half *Wbig, *hbig, *W1H, *encA, *embX, *WeB, *WihB;
    cudaGetSymbolAddress((void**)&enc_proj,  g_enc_proj);
    cudaGetSymbolAddress((void**)&gates_pre, g_gates_pre);
    cudaGetSymbolAddress((void**)&bsum,      g_bsum);
    cudaGetSymbolAddress((void**)&Wbig,      g_Wbig);
    cudaGetSymbolAddress((void**)&hbig,      g_hbig);
    cudaGetSymbolAddress((void**)&W1H,       g_W1H);
    cudaGetSymbolAddress((void**)&encA,      g_encA);
    cudaGetSymbolAddress((void**)&embX,      g_embX);
    cudaGetSymbolAddress((void**)&WeB,       g_WeB);
    cudaGetSymbolAddress((void**)&WihB,      g_WihB);
    float* big1; cudaGetSymbolAddress((void**)&big1, g_big1);

    // fork: all side streams join the capture BEFORE any of their work
    zero_state<<<256, 256>>>();
    cudaEventRecord(evStart, 0);
    cudaStreamWaitEvent(s2, evStart, 0);
    cudaStreamWaitEvent(s3, evStart, 0);
    cudaStreamWaitEvent(s4, evStart, 0);

    // s2: W_fc fp16 (feeds logits on both logits streams)
    wfc_conv<<<VPAD_, 512, 0, s2>>>(W_fc);
    cudaEventRecord(evW, s2);
    cudaStreamWaitEvent(s4, evW, 0);

    // s3: gates_pre pipeline
    bias_sum_perm<<<8, 256, 0, s3>>>(b_ih, b_hh);
    emb_gather<<<BT_, 512, 0, s3>>>(captions, emb);
    wih_emb_conv<<<4 * H_, 512, 0, s3>>>(W_ih);
    mma_gemm<<<dim3(16, T_), 256, SMEM_BYTES_, s3>>>(
        embX, WihB, bsum, gates_pre, 4L * H_, 4 * H_);
    cudaEventRecord(evG, s3);

    // s1: chain weights + enc_proj
    w1h_conv<<<2560, 512>>>(W_h, W_hh);
    w2_conv<<<2048, 512>>>(W_ih);
    h16_conv<<<H_, 512>>>(W_e, WeB);
    h16_conv<<<BL_, 512>>>(enc, encA);
    mma_gemm<<<dim3(4, BL_ / 128), 256, SMEM_BYTES_>>>(
        encA, WeB, nullptr, enc_proj, (long)H_, H_);

    cudaStream_t sL[2] = {s2, s4};
    for (int t = 0; t < T_; t++) {
        // gemm1: big1 = h(t) @ [W_h | perm(W_hh)]^T   (A = hbig slot t)
        mma_gemm<<<dim3(20, 1), 256, SMEM_BYTES_>>>(
            hbig + (size_t)t * B_ * 512, W1H, nullptr, big1, 2560L, 2560);
        attn_kernel<<<B_, 512>>>(enc, v_attn);
        if (t == 0) cudaStreamWaitEvent(0, evG, 0);   // join s3 (gates_pre)
        gemm2_lstm<<<dim3(16, 1), 256, SMEM_BYTES_>>>(t);
        cudaEventRecord(evH, 0);
        cudaStreamWaitEvent(sL[t & 1], evH, 0);
        // logits: single-term fp16, K=512, 79 CTAs, alternating streams
        mma_gemm<<<dim3(79, 1), 256, SMEM_BYTES_, sL[t & 1]>>>(
            hbig + (size_t)(t + 1) * B_ * 512, Wbig, b_fc,
            out + (size_t)t * V_, (long)(T_ * V_), V_);
    }
    cudaEventRecord(evJ2, s2);
    cudaStreamWaitEvent(0, evJ2, 0);
    cudaEventRecord(evJ4, s4);
    cudaStreamWaitEvent(0, evJ4, 0);
}